// round 15
// baseline (speedup 1.0000x reference)
#include <cuda_runtime.h>
#include <cuda_bf16.h>
#include <cstdint>

#define DD 64
#define RR 16
#define CAP 57344                  // per-relation segment capacity
#define TILE_M 160                 // 5 warps x 32 rows

typedef unsigned int u32;

// ---- static scratch (allocation-free rule) ----
__device__ float g_x1[(size_t)50048 * DD];                 // layer-1 output (L2-resident)
__device__ __nv_bfloat16 g_xs[(size_t)50048 * 128];        // per-node split: hi[64], lo[64]
__device__ uint2 g_Wf[2 * RR * 2048];                      // fragment-ordered W
__device__ int4  g_edge[(size_t)RR * CAP];                 // {src, dst, w_bits, 0}
__device__ u32   g_pos[RR];

__device__ __forceinline__ uint32_t smem_u32(const void* p) {
    uint32_t a;
    asm("{ .reg .u64 t; cvta.to.shared.u64 t, %1; cvt.u32.u64 %0, t; }" : "=r"(a) : "l"(p));
    return a;
}

__device__ __forceinline__ void ldsm_x4(uint32_t* r, uint32_t addr) {
    asm volatile("ldmatrix.sync.aligned.m8n8.x4.shared.b16 {%0,%1,%2,%3}, [%4];"
                 : "=r"(r[0]), "=r"(r[1]), "=r"(r[2]), "=r"(r[3]) : "r"(addr));
}

__device__ __forceinline__ void mma_bf16(float* c, const uint32_t* a, u32 b0, u32 b1) {
    asm volatile(
        "mma.sync.aligned.m16n8k16.row.col.f32.bf16.bf16.f32 "
        "{%0,%1,%2,%3}, {%4,%5,%6,%7}, {%8,%9}, {%0,%1,%2,%3};"
        : "+f"(c[0]), "+f"(c[1]), "+f"(c[2]), "+f"(c[3])
        : "r"(a[0]), "r"(a[1]), "r"(a[2]), "r"(a[3]), "r"(b0), "r"(b1));
}

__device__ __forceinline__ u32 pack_bf16x2(float a, float b) {
    u32 r; asm("cvt.rn.bf16x2.f32 %0, %1, %2;" : "=r"(r) : "f"(b), "f"(a)); return r;
}

__device__ __forceinline__ u32 pack2u(__nv_bfloat16 a, __nv_bfloat16 b) {
    return ((u32)__bfloat16_as_ushort(b) << 16) | __bfloat16_as_ushort(a);
}

__device__ __forceinline__ void cpasync16(u32 smem, const void* gmem) {
    asm volatile("cp.async.cg.shared.global [%0], [%1], 16;" :: "r"(smem), "l"(gmem) : "memory");
}

__device__ __forceinline__ void red2(float* p, float a, float b) {
    asm volatile("red.global.add.v2.f32 [%0], {%1, %2};"
                 :: "l"(p), "f"(a), "f"(b) : "memory");
}

// ---------------- W pre-convert into fragment order (+ init g_pos) ----------------
__global__ void convert_W(const float* __restrict__ W1, const float* __restrict__ W2)
{
    const int lr = blockIdx.x;               // 0..31
    const int layer = lr >> 4, r = lr & 15;
    if (lr == 0 && threadIdx.x < RR) g_pos[threadIdx.x] = threadIdx.x * CAP;
    const float* Wr = (layer ? W2 : W1) + (size_t)r * DD * DD;
    __shared__ float tile[DD][DD + 1];       // tile[k][o]
    const int tid = threadIdx.x;             // 256
    #pragma unroll
    for (int it = 0; it < 16; ++it) {
        int idx = it * 256 + tid;
        tile[idx >> 6][idx & 63] = Wr[idx];
    }
    __syncthreads();
    uint2* dst = g_Wf + (size_t)(layer * RR + r) * 2048;
    #pragma unroll
    for (int it = 0; it < 8; ++it) {
        int e = it * 256 + tid;              // [term][ks][tt][lane]
        int lane = e & 31;
        int tt   = (e >> 5) & 7;
        int ks   = (e >> 8) & 3;
        int term = (e >> 10) & 1;
        int o  = (lane >> 2) + 8 * tt;
        int kb = 2 * (lane & 3) + 16 * ks;
        float w0 = tile[kb][o],     w1 = tile[kb + 1][o];
        float w2 = tile[kb + 8][o], w3 = tile[kb + 9][o];
        __nv_bfloat16 h0 = __float2bfloat16_rn(w0), h1 = __float2bfloat16_rn(w1);
        __nv_bfloat16 h2 = __float2bfloat16_rn(w2), h3 = __float2bfloat16_rn(w3);
        uint2 v;
        if (term == 0) {
            v.x = pack2u(h0, h1); v.y = pack2u(h2, h3);
        } else {
            __nv_bfloat16 l0 = __float2bfloat16_rn(w0 - __bfloat162float(h0));
            __nv_bfloat16 l1 = __float2bfloat16_rn(w1 - __bfloat162float(h1));
            __nv_bfloat16 l2 = __float2bfloat16_rn(w2 - __bfloat162float(h2));
            __nv_bfloat16 l3 = __float2bfloat16_rn(w3 - __bfloat162float(h3));
            v.x = pack2u(l0, l1); v.y = pack2u(l2, l3);
        }
        dst[e] = v;
    }
}

// ---------------- per-node bf16 hi/lo split (+ fused zeroing) ----------------
template<bool L2>
__global__ void split_x(const float* __restrict__ x_in,
                        const float* __restrict__ bias,
                        float* __restrict__ zbuf, int N)
{
    const int idx = blockIdx.x * blockDim.x + threadIdx.x;   // one per 8 floats
    const int row = idx >> 3;
    const int c8  = idx & 7;
    if (row >= N) return;
    const float* src = L2 ? (const float*)g_x1 : x_in;
    float4 v0 = reinterpret_cast<const float4*>(src)[(size_t)row * 16 + c8 * 2];
    float4 v1 = reinterpret_cast<const float4*>(src)[(size_t)row * 16 + c8 * 2 + 1];
    if (L2) {
        int c = c8 * 8;
        v0.x = fmaxf(v0.x + bias[c+0], 0.f); v0.y = fmaxf(v0.y + bias[c+1], 0.f);
        v0.z = fmaxf(v0.z + bias[c+2], 0.f); v0.w = fmaxf(v0.w + bias[c+3], 0.f);
        v1.x = fmaxf(v1.x + bias[c+4], 0.f); v1.y = fmaxf(v1.y + bias[c+5], 0.f);
        v1.z = fmaxf(v1.z + bias[c+6], 0.f); v1.w = fmaxf(v1.w + bias[c+7], 0.f);
    }
    float4 z = make_float4(0.f, 0.f, 0.f, 0.f);
    float* zb = L2 ? zbuf : (float*)g_x1;
    reinterpret_cast<float4*>(zb)[(size_t)row * 16 + c8 * 2]     = z;
    reinterpret_cast<float4*>(zb)[(size_t)row * 16 + c8 * 2 + 1] = z;

    float f[8] = {v0.x, v0.y, v0.z, v0.w, v1.x, v1.y, v1.z, v1.w};
    u32 hi[4], lo[4];
    #pragma unroll
    for (int j = 0; j < 4; ++j) {
        hi[j] = pack_bf16x2(f[2*j], f[2*j+1]);
        float h0 = __uint_as_float(hi[j] << 16);
        float h1 = __uint_as_float(hi[j] & 0xFFFF0000u);
        lo[j] = pack_bf16x2(f[2*j] - h0, f[2*j+1] - h1);
    }
    uint4* dst = reinterpret_cast<uint4*>(g_xs) + (size_t)row * 16;
    dst[c8]     = make_uint4(hi[0], hi[1], hi[2], hi[3]);
    dst[c8 + 8] = make_uint4(lo[0], lo[1], lo[2], lo[3]);
}

// ---------------- single-pass fill into fixed per-relation segments ----------------
__global__ void fill_kernel(const int* __restrict__ ei, const int* __restrict__ et,
                            const float* __restrict__ pl, int E0, int nTot)
{
    __shared__ u32 h[RR];
    __shared__ u32 base16[RR];
    const int tid = threadIdx.x;
    if (tid < RR) h[tid] = 0;
    __syncthreads();
    const int b = blockIdx.x * 1024;
    int rel[4]; u32 rank[4];
    #pragma unroll
    for (int j = 0; j < 4; ++j) {
        int e = b + j * 256 + tid;
        rel[j] = -1;
        if (e < nTot) { rel[j] = et[e] & 15; rank[j] = atomicAdd(&h[rel[j]], 1u); }
    }
    __syncthreads();
    if (tid < RR) base16[tid] = h[tid] ? atomicAdd(&g_pos[tid], h[tid]) : 0u;
    __syncthreads();
    #pragma unroll
    for (int j = 0; j < 4; ++j) {
        if (rel[j] >= 0) {
            int e = b + j * 256 + tid;
            u32 p = base16[rel[j]] + rank[j];
            int s, d;
            if (e < E0) { s = ei[e]; d = ei[E0 + e]; }
            else        { s = e - E0; d = s; }
            float w = 1.0f / fmaxf(pl[e], 1e-9f);
            g_edge[p] = make_int4(s, d, __float_as_int(w), 0);
        }
    }
}

// ---------------- persistent fused edge GEMM + scatter ----------------
// 160 threads (5 warps x 32 rows). Warp-local pipeline; block sync only at
// relation boundaries. Fragment-ordered W (LDS.64 per B frag). Coalesced
// row-major gather. Direct red.v2 epilogue straight from MMA fragments.

#define XBUF  40960                // 160 rows x 256B (hi 20480 + lo 20480)
#define OFF_X    0                 // 2 bufs
#define OFF_W    81920             // 16384 (2048 uint2, fragment order)
#define OFF_MD   98304             // meta dst: int[2][160]
#define OFF_MW   99584             // meta w: float[2][160]
#define OFF_TB   100864            // s_tb[17], s_cnt[16]
#define SMEM_BYTES 101120
#define GRID_MMA 296

__global__ void __launch_bounds__(160, 2) edge_mma(
    int layer, float* __restrict__ out_p, int toG)
{
    extern __shared__ char sb[];
    const uint32_t sbase = smem_u32(sb);
    float* __restrict__ out = toG ? (float*)g_x1 : out_p;

    const int tid  = threadIdx.x;
    const int wid  = tid >> 5;
    const int lane = tid & 31;

    u32* s_tb  = (u32*)(sb + OFF_TB);        // [17]
    u32* s_cnt = s_tb + 17;                  // [16]

    // ---- derive tile table from g_pos (warp 0) ----
    if (wid == 0) {
        u32 c = (lane < RR) ? (g_pos[lane] - lane * CAP) : 0;
        u32 nt = (c + TILE_M - 1) / TILE_M;
        u32 tx = nt;
        #pragma unroll
        for (int s = 1; s < 16; s <<= 1) {
            u32 y = __shfl_up_sync(0xFFFFFFFFu, tx, s);
            if (lane >= s) tx += y;
        }
        if (lane < RR) { s_cnt[lane] = c; s_tb[lane] = tx - nt; }
        if (lane == RR - 1) s_tb[RR] = tx;
    }
    __syncthreads();

    const u32 ntiles = s_tb[RR];
    const u32 chunk  = (ntiles + gridDim.x - 1) / gridDim.x;
    const u32 t0 = blockIdx.x * chunk;
    const u32 t1 = min(t0 + chunk, ntiles);
    if (t0 >= t1) return;

    int*   meta_d = (int*)(sb + OFF_MD);
    float* meta_w = (float*)(sb + OFF_MW);

    auto tile_info = [&](u32 t, int& rel, int& start, int& cnt) {
        int r = 0;
        #pragma unroll
        for (int q = 1; q < RR; ++q) if (t >= s_tb[q]) r = q;
        rel = r;
        u32 loc = (t - s_tb[r]) * TILE_M;
        start = r * CAP + (int)loc;
        cnt = min(TILE_M, (int)(s_cnt[r] - loc));
    };

    // coalesced warp-local gather: 8 lanes per 128B row-half, 4 rows per instr.
    auto do_gather = [&](int srcnode, u32 xb) {
        const int ch = lane & 7;
        #pragma unroll
        for (int p = 0; p < 8; ++p) {
            int lr = p * 4 + (lane >> 3);            // local row 0..31
            int s  = __shfl_sync(0xFFFFFFFFu, srcnode, lr);
            int row = wid * 32 + lr;
            const char* gp = (const char*)g_xs + (size_t)s * 256;
            u32 dst = xb + (u32)(row * 128 + ((ch ^ (row & 7)) << 4));
            cpasync16(dst,         gp + ch * 16);          // hi
            cpasync16(dst + 20480, gp + 128 + ch * 16);    // lo
        }
    };

    // ---- prologue: prefetch tile t0 into buf 0 ----
    {
        int rel, start, cnt;
        tile_info(t0, rel, start, cnt);
        int4 em = make_int4(0, 0, 0, 0);     // invalid rows: src 0, dst 0, w 0
        if (tid < cnt) em = g_edge[start + tid];
        meta_d[tid] = em.y; meta_w[tid] = __int_as_float(em.z);
        do_gather(em.x, sbase + OFF_X);
        asm volatile("cp.async.commit_group;" ::: "memory");
    }

    int cur_rel = -1;
    const char* wf = sb + OFF_W;
    const int g  = lane >> 2;
    const int j2 = (lane & 3) * 2;

    for (u32 t = t0; t < t1; ++t) {
        const int buf = (int)((t - t0) & 1);
        int rel, start, cnt;
        tile_info(t, rel, start, cnt);

        asm volatile("cp.async.wait_group 0;" ::: "memory");

        if (rel != cur_rel) {                 // rare (relation boundary)
            __syncthreads();                  // old-W readers done
            const uint4* wsrc = reinterpret_cast<const uint4*>(
                g_Wf + (size_t)(layer * RR + rel) * 2048);
            for (int idx = tid; idx < 1024; idx += TILE_M)
                reinterpret_cast<uint4*>(sb + OFF_W)[idx] = wsrc[idx];
            cur_rel = rel;
            __syncthreads();                  // new W visible to all warps
        }
        __syncwarp();                         // warp-local gathers visible

        // prefetch meta for t+1 (LDG latency hides under MMA)
        const bool has_next = (t + 1 < t1);
        int4 em = make_int4(0, 0, 0, 0);
        if (has_next) {
            int nrel, nstart, ncnt;
            tile_info(t + 1, nrel, nstart, ncnt);
            if (tid < ncnt) em = g_edge[nstart + tid];
        }

        // ---- MMA on buf: warp owns rows [32*wid, 32*wid+32) ----
        const uint32_t xhi_base = sbase + OFF_X + buf * XBUF;
        const uint32_t xlo_base = xhi_base + 20480;

        float acc[2][8][4];
        #pragma unroll
        for (int mt = 0; mt < 2; ++mt)
            #pragma unroll
            for (int tt = 0; tt < 8; ++tt)
                #pragma unroll
                for (int j = 0; j < 4; ++j) acc[mt][tt][j] = 0.f;

        #pragma unroll
        for (int ks = 0; ks < 4; ++ks) {
            uint32_t ahi[2][4], alo[2][4];
            #pragma unroll
            for (int mt = 0; mt < 2; ++mt) {
                int row = wid * 32 + mt * 16 + (lane & 15);
                int c16 = ks * 2 + (lane >> 4);
                uint32_t off = (uint32_t)(row * 128 + ((c16 ^ (row & 7)) << 4));
                ldsm_x4(ahi[mt], xhi_base + off);
                ldsm_x4(alo[mt], xlo_base + off);
            }
            uint2 bh[8], bl[8];
            #pragma unroll
            for (int tt = 0; tt < 8; ++tt) {
                int ih = ((0 * 4 + ks) * 8 + tt) * 32 + lane;
                int il = ((1 * 4 + ks) * 8 + tt) * 32 + lane;
                bh[tt] = *reinterpret_cast<const uint2*>(wf + ih * 8);
                bl[tt] = *reinterpret_cast<const uint2*>(wf + il * 8);
            }
            #pragma unroll
            for (int mt = 0; mt < 2; ++mt)
                #pragma unroll
                for (int tt = 0; tt < 8; ++tt) {
                    mma_bf16(acc[mt][tt], ahi[mt], bh[tt].x, bh[tt].y);
                    mma_bf16(acc[mt][tt], alo[mt], bh[tt].x, bh[tt].y);
                    mma_bf16(acc[mt][tt], ahi[mt], bl[tt].x, bl[tt].y);
                }
        }

        // ---- issue gathers + meta for t+1 into buf^1 (overlap epilogue) ----
        if (has_next) {
            meta_d[(buf ^ 1) * TILE_M + tid] = em.y;
            meta_w[(buf ^ 1) * TILE_M + tid] = __int_as_float(em.z);
            do_gather(em.x, sbase + OFF_X + (buf ^ 1) * XBUF);
        }
        asm volatile("cp.async.commit_group;" ::: "memory");

        // ---- direct epilogue: red.v2 from fragments (w=0 rows add 0.0) ----
        #pragma unroll
        for (int mt = 0; mt < 2; ++mt) {
            int rowA = wid * 32 + mt * 16 + g;
            int rowB = rowA + 8;
            float wA = meta_w[buf * TILE_M + rowA];
            float wB = meta_w[buf * TILE_M + rowB];
            int   dA = meta_d[buf * TILE_M + rowA];
            int   dB = meta_d[buf * TILE_M + rowB];
            float* pA = &out[(size_t)dA * DD + j2];
            float* pB = &out[(size_t)dB * DD + j2];
            #pragma unroll
            for (int tt = 0; tt < 8; ++tt) {
                red2(pA + tt * 8, acc[mt][tt][0] * wA, acc[mt][tt][1] * wA);
                red2(pB + tt * 8, acc[mt][tt][2] * wB, acc[mt][tt][3] * wB);
            }
        }
    }
}

// ---------------- aux ----------------

__global__ void relu_bias_kernel(float* __restrict__ out,
                                 const float* __restrict__ bias, int n4)
{
    int f = blockIdx.x * blockDim.x + threadIdx.x;
    if (f >= n4) return;
    int c4 = (f & 15) << 2;
    float4 v = reinterpret_cast<float4*>(out)[f];
    v.x = fmaxf(v.x + bias[c4 + 0], 0.f);
    v.y = fmaxf(v.y + bias[c4 + 1], 0.f);
    v.z = fmaxf(v.z + bias[c4 + 2], 0.f);
    v.w = fmaxf(v.w + bias[c4 + 3], 0.f);
    reinterpret_cast<float4*>(out)[f] = v;
}

extern "C" void kernel_launch(void* const* d_in, const int* in_sizes, int n_in,
                              void* d_out, int out_size)
{
    const float* x   = (const float*)d_in[0];
    const int*   ei  = (const int*)  d_in[1];
    const int*   et  = (const int*)  d_in[2];
    const float* pl  = (const float*)d_in[3];
    const float* w1  = (const float*)d_in[4];
    const float* b1  = (const float*)d_in[5];
    const float* w2  = (const float*)d_in[6];
    const float* b2  = (const float*)d_in[7];

    const int N    = in_sizes[0] / DD;
    const int E0   = in_sizes[1] / 2;
    const int nTot = in_sizes[2];

    const int fgrid  = (nTot + 1023) / 1024;
    const int n4     = N * (DD / 4);
    const int splitG = (N * 8 + 255) / 256;

    cudaFuncSetAttribute(edge_mma,
                         cudaFuncAttributeMaxDynamicSharedMemorySize, SMEM_BYTES);

    // prep: W conversion (+pos init), single-pass fill, split(+zero g_x1)
    convert_W<<<32, 256>>>(w1, w2);
    fill_kernel<<<fgrid, 256>>>(ei, et, pl, E0, nTot);
    split_x<false><<<splitG, 256>>>(x, nullptr, nullptr, N);

    // layer 1: fused transform+scatter into g_x1
    edge_mma<<<GRID_MMA, TILE_M, SMEM_BYTES>>>(0, nullptr, 1);

    // layer 2: split relu(x1+b1) (+zero d_out), fused transform+scatter, epilogue
    split_x<true><<<splitG, 256>>>(nullptr, b1, (float*)d_out, N);
    edge_mma<<<GRID_MMA, TILE_M, SMEM_BYTES>>>(1, (float*)d_out, 0);
    relu_bias_kernel<<<(n4 + 255) / 256, 256>>>((float*)d_out, b2, n4);
}

// round 16
// speedup vs baseline: 1.1605x; 1.1605x over previous
#include <cuda_runtime.h>
#include <cuda_bf16.h>
#include <cstdint>

#define DD 64
#define RR 16
#define CAP 57344                  // per-relation segment capacity
#define TILE_M 128                 // 4 warps x 32 rows

typedef unsigned int u32;

// ---- static scratch (allocation-free rule) ----
__device__ float g_x1[(size_t)50048 * DD];                 // layer-1 output (L2-resident)
__device__ __nv_bfloat16 g_xs[(size_t)50048 * 128];        // per-node split: hi[64], lo[64]
__device__ uint2 g_Wf[2 * RR * 2048];                      // fragment-ordered W
__device__ int4  g_edge[(size_t)RR * CAP];                 // {src, dst, w_bits, 0}
__device__ u32   g_pos[RR];

__device__ __forceinline__ uint32_t smem_u32(const void* p) {
    uint32_t a;
    asm("{ .reg .u64 t; cvta.to.shared.u64 t, %1; cvt.u32.u64 %0, t; }" : "=r"(a) : "l"(p));
    return a;
}

__device__ __forceinline__ void ldsm_x4(uint32_t* r, uint32_t addr) {
    asm volatile("ldmatrix.sync.aligned.m8n8.x4.shared.b16 {%0,%1,%2,%3}, [%4];"
                 : "=r"(r[0]), "=r"(r[1]), "=r"(r[2]), "=r"(r[3]) : "r"(addr));
}

__device__ __forceinline__ void mma_bf16(float* c, const uint32_t* a, u32 b0, u32 b1) {
    asm volatile(
        "mma.sync.aligned.m16n8k16.row.col.f32.bf16.bf16.f32 "
        "{%0,%1,%2,%3}, {%4,%5,%6,%7}, {%8,%9}, {%0,%1,%2,%3};"
        : "+f"(c[0]), "+f"(c[1]), "+f"(c[2]), "+f"(c[3])
        : "r"(a[0]), "r"(a[1]), "r"(a[2]), "r"(a[3]), "r"(b0), "r"(b1));
}

__device__ __forceinline__ u32 pack_bf16x2(float a, float b) {
    u32 r; asm("cvt.rn.bf16x2.f32 %0, %1, %2;" : "=r"(r) : "f"(b), "f"(a)); return r;
}

__device__ __forceinline__ u32 pack2u(__nv_bfloat16 a, __nv_bfloat16 b) {
    return ((u32)__bfloat16_as_ushort(b) << 16) | __bfloat16_as_ushort(a);
}

__device__ __forceinline__ void cpasync16(u32 smem, const void* gmem) {
    asm volatile("cp.async.cg.shared.global [%0], [%1], 16;" :: "r"(smem), "l"(gmem) : "memory");
}

// ---------------- W pre-convert into fragment order (+ init g_pos) ----------------
__global__ void convert_W(const float* __restrict__ W1, const float* __restrict__ W2)
{
    const int lr = blockIdx.x;               // 0..31
    const int layer = lr >> 4, r = lr & 15;
    if (lr == 0 && threadIdx.x < RR) g_pos[threadIdx.x] = threadIdx.x * CAP;
    const float* Wr = (layer ? W2 : W1) + (size_t)r * DD * DD;
    __shared__ float tile[DD][DD + 1];       // tile[k][o]
    const int tid = threadIdx.x;             // 256
    #pragma unroll
    for (int it = 0; it < 16; ++it) {
        int idx = it * 256 + tid;
        tile[idx >> 6][idx & 63] = Wr[idx];
    }
    __syncthreads();
    uint2* dst = g_Wf + (size_t)(layer * RR + r) * 2048;
    #pragma unroll
    for (int it = 0; it < 8; ++it) {
        int e = it * 256 + tid;              // [term][ks][tt][lane]
        int lane = e & 31;
        int tt   = (e >> 5) & 7;
        int ks   = (e >> 8) & 3;
        int term = (e >> 10) & 1;
        int o  = (lane >> 2) + 8 * tt;
        int kb = 2 * (lane & 3) + 16 * ks;
        float w0 = tile[kb][o],     w1 = tile[kb + 1][o];
        float w2 = tile[kb + 8][o], w3 = tile[kb + 9][o];
        __nv_bfloat16 h0 = __float2bfloat16_rn(w0), h1 = __float2bfloat16_rn(w1);
        __nv_bfloat16 h2 = __float2bfloat16_rn(w2), h3 = __float2bfloat16_rn(w3);
        uint2 v;
        if (term == 0) {
            v.x = pack2u(h0, h1); v.y = pack2u(h2, h3);
        } else {
            __nv_bfloat16 l0 = __float2bfloat16_rn(w0 - __bfloat162float(h0));
            __nv_bfloat16 l1 = __float2bfloat16_rn(w1 - __bfloat162float(h1));
            __nv_bfloat16 l2 = __float2bfloat16_rn(w2 - __bfloat162float(h2));
            __nv_bfloat16 l3 = __float2bfloat16_rn(w3 - __bfloat162float(h3));
            v.x = pack2u(l0, l1); v.y = pack2u(l2, l3);
        }
        dst[e] = v;
    }
}

// ---------------- per-node bf16 hi/lo split (+ fused zeroing) ----------------
template<bool L2>
__global__ void split_x(const float* __restrict__ x_in,
                        const float* __restrict__ bias,
                        float* __restrict__ zbuf, int N)
{
    const int idx = blockIdx.x * blockDim.x + threadIdx.x;   // one per 8 floats
    const int row = idx >> 3;
    const int c8  = idx & 7;
    if (row >= N) return;
    const float* src = L2 ? (const float*)g_x1 : x_in;
    float4 v0 = reinterpret_cast<const float4*>(src)[(size_t)row * 16 + c8 * 2];
    float4 v1 = reinterpret_cast<const float4*>(src)[(size_t)row * 16 + c8 * 2 + 1];
    if (L2) {
        int c = c8 * 8;
        v0.x = fmaxf(v0.x + bias[c+0], 0.f); v0.y = fmaxf(v0.y + bias[c+1], 0.f);
        v0.z = fmaxf(v0.z + bias[c+2], 0.f); v0.w = fmaxf(v0.w + bias[c+3], 0.f);
        v1.x = fmaxf(v1.x + bias[c+4], 0.f); v1.y = fmaxf(v1.y + bias[c+5], 0.f);
        v1.z = fmaxf(v1.z + bias[c+6], 0.f); v1.w = fmaxf(v1.w + bias[c+7], 0.f);
    }
    float4 z = make_float4(0.f, 0.f, 0.f, 0.f);
    float* zb = L2 ? zbuf : (float*)g_x1;
    reinterpret_cast<float4*>(zb)[(size_t)row * 16 + c8 * 2]     = z;
    reinterpret_cast<float4*>(zb)[(size_t)row * 16 + c8 * 2 + 1] = z;

    float f[8] = {v0.x, v0.y, v0.z, v0.w, v1.x, v1.y, v1.z, v1.w};
    u32 hi[4], lo[4];
    #pragma unroll
    for (int j = 0; j < 4; ++j) {
        hi[j] = pack_bf16x2(f[2*j], f[2*j+1]);
        float h0 = __uint_as_float(hi[j] << 16);
        float h1 = __uint_as_float(hi[j] & 0xFFFF0000u);
        lo[j] = pack_bf16x2(f[2*j] - h0, f[2*j+1] - h1);
    }
    uint4* dst = reinterpret_cast<uint4*>(g_xs) + (size_t)row * 16;
    dst[c8]     = make_uint4(hi[0], hi[1], hi[2], hi[3]);
    dst[c8 + 8] = make_uint4(lo[0], lo[1], lo[2], lo[3]);
}

// ---------------- single-pass fill into fixed per-relation segments ----------------
__global__ void fill_kernel(const int* __restrict__ ei, const int* __restrict__ et,
                            const float* __restrict__ pl, int E0, int nTot)
{
    __shared__ u32 h[RR];
    __shared__ u32 base16[RR];
    const int tid = threadIdx.x;
    if (tid < RR) h[tid] = 0;
    __syncthreads();
    const int b = blockIdx.x * 1024;
    int rel[4]; u32 rank[4];
    #pragma unroll
    for (int j = 0; j < 4; ++j) {
        int e = b + j * 256 + tid;
        rel[j] = -1;
        if (e < nTot) { rel[j] = et[e] & 15; rank[j] = atomicAdd(&h[rel[j]], 1u); }
    }
    __syncthreads();
    if (tid < RR) base16[tid] = h[tid] ? atomicAdd(&g_pos[tid], h[tid]) : 0u;
    __syncthreads();
    #pragma unroll
    for (int j = 0; j < 4; ++j) {
        if (rel[j] >= 0) {
            int e = b + j * 256 + tid;
            u32 p = base16[rel[j]] + rank[j];
            int s, d;
            if (e < E0) { s = ei[e]; d = ei[E0 + e]; }
            else        { s = e - E0; d = s; }
            float w = 1.0f / fmaxf(pl[e], 1e-9f);
            g_edge[p] = make_int4(s, d, __float_as_int(w), 0);
        }
    }
}

// ---------------- persistent fused edge GEMM + scatter ----------------
// 128 threads (4 warps x 32 rows). Warp-local pipeline; block sync only at
// relation boundaries. B-hi fragments register-resident (reloaded per relation);
// B-lo from fragment-ordered smem. Coalesced row-major gather. Staging + red.v4.

#define XBUF  32768                // 128 rows x 256B (hi 16384 + lo 16384)
#define OFF_X    0                 // 2 bufs
#define OFF_W    65536             // 16384 (2048 uint2, fragment order)
#define OFF_MD   81920             // meta dst: int[2][128]
#define OFF_MW   82944             // meta w: float[2][128]
#define OFF_TB   83968             // s_tb[17], s_cnt[16]
#define SMEM_BYTES 84224
#define GRID_MMA 296

__global__ void __launch_bounds__(TILE_M, 2) edge_mma(
    int layer, float* __restrict__ out_p, int toG)
{
    extern __shared__ char sb[];
    const uint32_t sbase = smem_u32(sb);
    float* __restrict__ out = toG ? (float*)g_x1 : out_p;

    const int tid  = threadIdx.x;
    const int wid  = tid >> 5;
    const int lane = tid & 31;

    u32* s_tb  = (u32*)(sb + OFF_TB);        // [17]
    u32* s_cnt = s_tb + 17;                  // [16]

    // ---- derive tile table from g_pos (warp 0) ----
    if (wid == 0) {
        u32 c = (lane < RR) ? (g_pos[lane] - lane * CAP) : 0;
        u32 nt = (c + TILE_M - 1) / TILE_M;
        u32 tx = nt;
        #pragma unroll
        for (int s = 1; s < 16; s <<= 1) {
            u32 y = __shfl_up_sync(0xFFFFFFFFu, tx, s);
            if (lane >= s) tx += y;
        }
        if (lane < RR) { s_cnt[lane] = c; s_tb[lane] = tx - nt; }
        if (lane == RR - 1) s_tb[RR] = tx;
    }
    __syncthreads();

    const u32 ntiles = s_tb[RR];
    const u32 chunk  = (ntiles + gridDim.x - 1) / gridDim.x;
    const u32 t0 = blockIdx.x * chunk;
    const u32 t1 = min(t0 + chunk, ntiles);
    if (t0 >= t1) return;

    int*   meta_d = (int*)(sb + OFF_MD);
    float* meta_w = (float*)(sb + OFF_MW);

    auto tile_info = [&](u32 t, int& rel, int& start, int& cnt) {
        int r = 0;
        #pragma unroll
        for (int q = 1; q < RR; ++q) if (t >= s_tb[q]) r = q;
        rel = r;
        u32 loc = (t - s_tb[r]) * TILE_M;
        start = r * CAP + (int)loc;
        cnt = min(TILE_M, (int)(s_cnt[r] - loc));
    };

    // coalesced warp-local gather: 8 lanes per 128B row-half, 4 rows per instr.
    auto do_gather = [&](int srcnode, u32 xb) {
        const int ch = lane & 7;
        #pragma unroll
        for (int p = 0; p < 8; ++p) {
            int lr = p * 4 + (lane >> 3);            // local row 0..31
            int s  = __shfl_sync(0xFFFFFFFFu, srcnode, lr);
            int row = wid * 32 + lr;
            const char* gp = (const char*)g_xs + (size_t)s * 256;
            u32 dst = xb + (u32)(row * 128 + ((ch ^ (row & 7)) << 4));
            cpasync16(dst,         gp + ch * 16);          // hi
            cpasync16(dst + 16384, gp + 128 + ch * 16);    // lo
        }
    };

    // ---- prologue: prefetch tile t0 into buf 0 ----
    {
        int rel, start, cnt;
        tile_info(t0, rel, start, cnt);
        int4 em = make_int4(0, 0, 0, 0);     // invalid rows: src 0, dst 0, w 0
        if (tid < cnt) em = g_edge[start + tid];
        meta_d[tid] = em.y; meta_w[tid] = __int_as_float(em.z);
        do_gather(em.x, sbase + OFF_X);
        asm volatile("cp.async.commit_group;" ::: "memory");
    }

    int cur_rel = -1;
    const char* wf = sb + OFF_W;
    uint2 bhr[4][8];                          // register-resident B-hi fragments

    for (u32 t = t0; t < t1; ++t) {
        const int buf = (int)((t - t0) & 1);
        int rel, start, cnt;
        tile_info(t, rel, start, cnt);

        asm volatile("cp.async.wait_group 0;" ::: "memory");

        if (rel != cur_rel) {                 // rare (relation boundary)
            __syncthreads();                  // old-W readers done
            const uint4* wsrc = reinterpret_cast<const uint4*>(
                g_Wf + (size_t)(layer * RR + rel) * 2048);
            for (int idx = tid; idx < 1024; idx += TILE_M)
                reinterpret_cast<uint4*>(sb + OFF_W)[idx] = wsrc[idx];
            cur_rel = rel;
            __syncthreads();                  // new W visible to all warps
            // hoist B-hi fragments into registers (once per relation)
            #pragma unroll
            for (int ks = 0; ks < 4; ++ks)
                #pragma unroll
                for (int tt = 0; tt < 8; ++tt) {
                    int ih = ((0 * 4 + ks) * 8 + tt) * 32 + lane;
                    bhr[ks][tt] = *reinterpret_cast<const uint2*>(wf + ih * 8);
                }
        }
        __syncwarp();                         // warp-local gathers visible

        // prefetch meta for t+1 (LDG latency hides under MMA)
        const bool has_next = (t + 1 < t1);
        int4 em = make_int4(0, 0, 0, 0);
        if (has_next) {
            int nrel, nstart, ncnt;
            tile_info(t + 1, nrel, nstart, ncnt);
            if (tid < ncnt) em = g_edge[nstart + tid];
        }

        // ---- MMA on buf: warp owns rows [32*wid, 32*wid+32) ----
        const uint32_t xhi_base = sbase + OFF_X + buf * XBUF;
        const uint32_t xlo_base = xhi_base + 16384;

        float acc[2][8][4];
        #pragma unroll
        for (int mt = 0; mt < 2; ++mt)
            #pragma unroll
            for (int tt = 0; tt < 8; ++tt)
                #pragma unroll
                for (int j = 0; j < 4; ++j) acc[mt][tt][j] = 0.f;

        #pragma unroll
        for (int ks = 0; ks < 4; ++ks) {
            uint32_t ahi[2][4], alo[2][4];
            #pragma unroll
            for (int mt = 0; mt < 2; ++mt) {
                int row = wid * 32 + mt * 16 + (lane & 15);
                int c16 = ks * 2 + (lane >> 4);
                uint32_t off = (uint32_t)(row * 128 + ((c16 ^ (row & 7)) << 4));
                ldsm_x4(ahi[mt], xhi_base + off);
                ldsm_x4(alo[mt], xlo_base + off);
            }
            uint2 bl[8];
            #pragma unroll
            for (int tt = 0; tt < 8; ++tt) {
                int il = ((1 * 4 + ks) * 8 + tt) * 32 + lane;
                bl[tt] = *reinterpret_cast<const uint2*>(wf + il * 8);
            }
            #pragma unroll
            for (int mt = 0; mt < 2; ++mt)
                #pragma unroll
                for (int tt = 0; tt < 8; ++tt) {
                    mma_bf16(acc[mt][tt], ahi[mt], bhr[ks][tt].x, bhr[ks][tt].y);
                    mma_bf16(acc[mt][tt], alo[mt], bhr[ks][tt].x, bhr[ks][tt].y);
                    mma_bf16(acc[mt][tt], ahi[mt], bl[tt].x, bl[tt].y);
                }
        }

        // ---- issue gathers + meta for t+1 into buf^1 (overlap epilogue) ----
        if (has_next) {
            meta_d[(buf ^ 1) * TILE_M + tid] = em.y;
            meta_w[(buf ^ 1) * TILE_M + tid] = __int_as_float(em.z);
            do_gather(em.x, sbase + OFF_X + (buf ^ 1) * XBUF);
        }
        asm volatile("cp.async.commit_group;" ::: "memory");

        __syncwarp();    // warp's MMA reads of buf done -> reuse own chunks

        // ---- warp-local staging: mt=0 -> own hi chunk, mt=1 -> own lo chunk ----
        #pragma unroll
        for (int mt = 0; mt < 2; ++mt) {
            float* stgc = reinterpret_cast<float*>(sb + OFF_X + buf * XBUF +
                                                   mt * 16384 + wid * 4096);
            int rA16 = (lane >> 2);
            int rB16 = rA16 + 8;
            int rowA = mt * 16 + rA16;
            int sw = (rowA & 7) << 3;
            #pragma unroll
            for (int tt = 0; tt < 8; ++tt) {
                int col = tt * 8 + 2 * (lane & 3);
                *reinterpret_cast<float2*>(&stgc[rA16 * 64 + (col ^ sw)]) =
                    make_float2(acc[mt][tt][0], acc[mt][tt][1]);
                *reinterpret_cast<float2*>(&stgc[rB16 * 64 + (col ^ sw)]) =
                    make_float2(acc[mt][tt][2], acc[mt][tt][3]);
            }
        }
        __syncwarp();

        // ---- epilogue: scale by 1/pl, red.v4 into out[dst] (L2-resident) ----
        #pragma unroll
        for (int mt = 0; mt < 2; ++mt) {
            const float* stgc = reinterpret_cast<const float*>(sb + OFF_X + buf * XBUF +
                                                               mt * 16384 + wid * 4096);
            #pragma unroll
            for (int p = 0; p < 2; ++p) {
                int lr16 = p * 8 + (lane >> 2);
                int lrow = mt * 16 + lr16;
                int grow = wid * 32 + lrow;
                if (grow < cnt) {
                    float w = meta_w[buf * TILE_M + grow];
                    int   d = meta_d[buf * TILE_M + grow];
                    float* pdst = &out[(size_t)d * DD];
                    #pragma unroll
                    for (int q = 0; q < 4; ++q) {
                        int c4 = (lane & 3) + q * 4;
                        int cc = (c4 * 4) ^ ((lrow & 7) << 3);
                        float4 v = *reinterpret_cast<const float4*>(&stgc[lr16 * 64 + cc]);
                        v.x *= w; v.y *= w; v.z *= w; v.w *= w;
                        asm volatile("red.global.add.v4.f32 [%0], {%1, %2, %3, %4};"
                                     :: "l"(pdst + c4 * 4), "f"(v.x), "f"(v.y), "f"(v.z), "f"(v.w)
                                     : "memory");
                    }
                }
            }
        }
    }
}

// ---------------- aux ----------------

__global__ void relu_bias_kernel(float* __restrict__ out,
                                 const float* __restrict__ bias, int n4)
{
    int f = blockIdx.x * blockDim.x + threadIdx.x;
    if (f >= n4) return;
    int c4 = (f & 15) << 2;
    float4 v = reinterpret_cast<float4*>(out)[f];
    v.x = fmaxf(v.x + bias[c4 + 0], 0.f);
    v.y = fmaxf(v.y + bias[c4 + 1], 0.f);
    v.z = fmaxf(v.z + bias[c4 + 2], 0.f);
    v.w = fmaxf(v.w + bias[c4 + 3], 0.f);
    reinterpret_cast<float4*>(out)[f] = v;
}

extern "C" void kernel_launch(void* const* d_in, const int* in_sizes, int n_in,
                              void* d_out, int out_size)
{
    const float* x   = (const float*)d_in[0];
    const int*   ei  = (const int*)  d_in[1];
    const int*   et  = (const int*)  d_in[2];
    const float* pl  = (const float*)d_in[3];
    const float* w1  = (const float*)d_in[4];
    const float* b1  = (const float*)d_in[5];
    const float* w2  = (const float*)d_in[6];
    const float* b2  = (const float*)d_in[7];

    const int N    = in_sizes[0] / DD;
    const int E0   = in_sizes[1] / 2;
    const int nTot = in_sizes[2];

    const int fgrid  = (nTot + 1023) / 1024;
    const int n4     = N * (DD / 4);
    const int splitG = (N * 8 + 255) / 256;

    cudaFuncSetAttribute(edge_mma,
                         cudaFuncAttributeMaxDynamicSharedMemorySize, SMEM_BYTES);

    // prep: W conversion (+pos init), single-pass fill, split(+zero g_x1)
    convert_W<<<32, 256>>>(w1, w2);
    fill_kernel<<<fgrid, 256>>>(ei, et, pl, E0, nTot);
    split_x<false><<<splitG, 256>>>(x, nullptr, nullptr, N);

    // layer 1: fused transform+scatter into g_x1
    edge_mma<<<GRID_MMA, TILE_M, SMEM_BYTES>>>(0, nullptr, 1);

    // layer 2: split relu(x1+b1) (+zero d_out), fused transform+scatter, epilogue
    split_x<true><<<splitG, 256>>>(nullptr, b1, (float*)d_out, N);
    edge_mma<<<GRID_MMA, TILE_M, SMEM_BYTES>>>(1, (float*)d_out, 0);
    relu_bias_kernel<<<(n4 + 255) / 256, 256>>>((float*)d_out, b2, n4);
}